// round 8
// baseline (speedup 1.0000x reference)
#include <cuda_runtime.h>
#include <cuda_bf16.h>

constexpr int NN  = 10000;
constexpr int NE  = 640000;
constexpr int C_IN  = 128;
constexpr int C_HID = 128;
constexpr int C_OUT = 64;

struct __align__(8) Edge { int s; float c; };

// Scratch (device globals — no allocation allowed)
__device__ __align__(256) float g_deg [NN];
__device__ __align__(256) float g_dinv[NN];
__device__ __align__(256) int   g_count[NN];
__device__ __align__(256) int   g_rowptr[NN + 1];
__device__ __align__(256) int   g_sd  [NE];       // packed (s | d<<16)
__device__ __align__(256) int   g_rank[NE];
__device__ __align__(256) Edge  g_csr [NE];
__device__ __align__(256) float g_xw  [NN * C_HID];  // x @ W1 (unscaled)
__device__ __align__(256) float g_h   [NN * C_HID];  // relu(layer1 out)
__device__ __align__(256) float g_hw  [NN * C_OUT];  // h @ W2 (unscaled)

// edge_index dtype: 0 -> int64 (odd 32-bit words all zero), 1 -> int32.
__device__ int g_odd_nonzero;

__device__ __forceinline__ int load_idx(const int* __restrict__ ei32, long pos) {
    return (g_odd_nonzero == 0) ? ei32[2 * pos] : ei32[pos];
}

// ---------------------------------------------------------------------------
// zero counters/degree + detect dtype
// ---------------------------------------------------------------------------
__global__ void k_zero_detect(const int* __restrict__ ei32) {
    int i = blockIdx.x * blockDim.x + threadIdx.x;
    if (i < NN) { g_count[i] = 0; g_deg[i] = 1.0f; }  // 1.0 = self-loop weight
    if (i < 2048) {
        if (ei32[2 * i + 1] != 0) atomicOr(&g_odd_nonzero, 1);
    }
}

// ---------------------------------------------------------------------------
// count + rank + pack + weighted degree (REDG for deg, 1 returning atomic)
// ---------------------------------------------------------------------------
__global__ void k_count(const int* __restrict__ ei32,
                        const float* __restrict__ w) {
    int e = blockIdx.x * blockDim.x + threadIdx.x;
    if (e < NE) {
        int s = load_idx(ei32, e);
        int d = load_idx(ei32, (long)NE + e);
        s = min(max(s, 0), NN - 1);
        d = min(max(d, 0), NN - 1);
        g_sd[e] = s | (d << 16);
        g_rank[e] = atomicAdd(&g_count[d], 1);
        atomicAdd(&g_deg[d], w[e]);   // no return -> REDG
    }
}

// elementwise dinv (runs on side stream, overlapped with scan+fill)
__global__ void k_dinv_ew() {
    int i = blockIdx.x * blockDim.x + threadIdx.x;
    if (i < NN) g_dinv[i] = rsqrtf(g_deg[i]);
}

// warp-shuffle exclusive scan of g_count -> g_rowptr (1024 thr, 2 barriers)
__global__ void k_scan() {
    constexpr int T = 1024, ITEMS = 10;   // 1024*10 >= 10000
    __shared__ int wsum[32];
    int t = threadIdx.x;
    int lane = t & 31;
    int wid  = t >> 5;

    int base = t * ITEMS;
    int local[ITEMS];
    int sum = 0;
#pragma unroll
    for (int i = 0; i < ITEMS; i++) {
        int idx = base + i;
        int v = (idx < NN) ? g_count[idx] : 0;
        local[i] = sum;
        sum += v;
    }
    int tsum = sum;

    // inclusive warp scan of tsum
    int incl = tsum;
#pragma unroll
    for (int off = 1; off < 32; off <<= 1) {
        int v = __shfl_up_sync(0xFFFFFFFF, incl, off);
        if (lane >= off) incl += v;
    }
    if (lane == 31) wsum[wid] = incl;
    __syncthreads();
    if (wid == 0) {
        int v = wsum[lane];
        int s = v;
#pragma unroll
        for (int off = 1; off < 32; off <<= 1) {
            int u = __shfl_up_sync(0xFFFFFFFF, s, off);
            if (lane >= off) s += u;
        }
        wsum[lane] = s;   // inclusive over warps
    }
    __syncthreads();

    int warpBase = (wid > 0) ? wsum[wid - 1] : 0;
    int texcl = warpBase + incl - tsum;   // exclusive prefix for this thread
#pragma unroll
    for (int i = 0; i < ITEMS; i++) {
        int idx = base + i;
        if (idx < NN) g_rowptr[idx] = texcl + local[i];
    }
    if (t == T - 1) g_rowptr[NN] = wsum[31];
}

// fill CSR (no atomics)
__global__ void k_fill(const float* __restrict__ w) {
    int e = blockIdx.x * blockDim.x + threadIdx.x;
    if (e < NE) {
        int sd = g_sd[e];
        int s = sd & 0xFFFF;
        int d = sd >> 16;
        int pos = g_rowptr[d] + g_rank[e];
        Edge ed; ed.s = s; ed.c = w[e];
        g_csr[pos] = ed;
    }
}

// ---------------------------------------------------------------------------
// fp32 tiled GEMM (pure):  C = A @ B
// ---------------------------------------------------------------------------
__device__ __forceinline__ void gemm_body(const float* __restrict__ A,
                                          const float* __restrict__ B,
                                          float* __restrict__ C,
                                          int M, int N, int K) {
    constexpr int BM = 64, BN = 64, BK = 16;
    __shared__ float As[BK][BM];
    __shared__ float Bs[BK][BN];

    int rowBase = blockIdx.x * BM;
    int colBase = blockIdx.y * BN;
    int tx = threadIdx.x % 16;
    int ty = threadIdx.x / 16;

    float acc[4][4];
#pragma unroll
    for (int m = 0; m < 4; m++)
#pragma unroll
        for (int n = 0; n < 4; n++) acc[m][n] = 0.0f;

    for (int k0 = 0; k0 < K; k0 += BK) {
        for (int i = threadIdx.x; i < BM * BK; i += 256) {
            int r = i / BK, c = i % BK;
            int gr = rowBase + r;
            As[c][r] = (gr < M) ? A[(long)gr * K + k0 + c] : 0.0f;
        }
        for (int i = threadIdx.x; i < BK * BN; i += 256) {
            int r = i / BN, c = i % BN;
            Bs[r][c] = B[(long)(k0 + r) * N + colBase + c];
        }
        __syncthreads();

#pragma unroll
        for (int k = 0; k < BK; k++) {
            float a[4], b[4];
#pragma unroll
            for (int m = 0; m < 4; m++) a[m] = As[k][ty * 4 + m];
#pragma unroll
            for (int n = 0; n < 4; n++) b[n] = Bs[k][tx * 4 + n];
#pragma unroll
            for (int m = 0; m < 4; m++)
#pragma unroll
                for (int n = 0; n < 4; n++) acc[m][n] += a[m] * b[n];
        }
        __syncthreads();
    }

#pragma unroll
    for (int m = 0; m < 4; m++) {
        int gr = rowBase + ty * 4 + m;
        if (gr < M) {
#pragma unroll
            for (int n = 0; n < 4; n++)
                C[(long)gr * N + colBase + tx * 4 + n] = acc[m][n];
        }
    }
}

__global__ void k_gemm1(const float* __restrict__ x,
                        const float* __restrict__ W1) {
    gemm_body(x, W1, g_xw, NN, C_HID, C_IN);
}
__global__ void k_gemm2(const float* __restrict__ W2) {
    gemm_body(g_h, W2, g_hw, NN, C_OUT, C_HID);
}

// ---------------------------------------------------------------------------
// warp-per-node gather-aggregate; dinv applied at staging + epilogue
//   out[d,:] = relu( dinv[d]*( dinv[d]*xw[d,:] + sum_e (w_e*dinv[s])*xw[s,:] ) + b )
// ---------------------------------------------------------------------------
__global__ void __launch_bounds__(256) k_agg1(const float* __restrict__ b1) {
    __shared__ Edge tile[8][32];
    int wid  = threadIdx.x >> 5;
    int lane = threadIdx.x & 31;
    int node = blockIdx.x * 8 + wid;
    if (node >= NN) return;

    const float4* xw4 = reinterpret_cast<const float4*>(g_xw);
    float di = g_dinv[node];
    float4 self = xw4[node * 32 + lane];
    float4 acc0 = make_float4(di * self.x, di * self.y, di * self.z, di * self.w);
    float4 acc1 = make_float4(0.f, 0.f, 0.f, 0.f);

    int beg = g_rowptr[node], end = g_rowptr[node + 1];
    for (int t = beg; t < end; t += 32) {
        int n = min(32, end - t);
        Edge e;
        if (t + lane < end) {
            e = g_csr[t + lane];
            e.c *= g_dinv[e.s];
        }
        __syncwarp();
        if (t + lane < end) tile[wid][lane] = e;
        __syncwarp();
        if (n == 32) {
            for (int j = 0; j < 32; j += 4) {
                Edge e0 = tile[wid][j + 0];
                Edge e1 = tile[wid][j + 1];
                Edge e2 = tile[wid][j + 2];
                Edge e3 = tile[wid][j + 3];
                float4 v0 = xw4[e0.s * 32 + lane];
                float4 v1 = xw4[e1.s * 32 + lane];
                float4 v2 = xw4[e2.s * 32 + lane];
                float4 v3 = xw4[e3.s * 32 + lane];
                acc0.x += e0.c * v0.x; acc0.y += e0.c * v0.y;
                acc0.z += e0.c * v0.z; acc0.w += e0.c * v0.w;
                acc1.x += e1.c * v1.x; acc1.y += e1.c * v1.y;
                acc1.z += e1.c * v1.z; acc1.w += e1.c * v1.w;
                acc0.x += e2.c * v2.x; acc0.y += e2.c * v2.y;
                acc0.z += e2.c * v2.z; acc0.w += e2.c * v2.w;
                acc1.x += e3.c * v3.x; acc1.y += e3.c * v3.y;
                acc1.z += e3.c * v3.z; acc1.w += e3.c * v3.w;
            }
        } else {
            for (int j = 0; j < n; j++) {
                Edge e0 = tile[wid][j];
                float4 v = xw4[e0.s * 32 + lane];
                acc0.x += e0.c * v.x; acc0.y += e0.c * v.y;
                acc0.z += e0.c * v.z; acc0.w += e0.c * v.w;
            }
        }
    }

    float4 b = reinterpret_cast<const float4*>(b1)[lane];
    float4 r;
    r.x = fmaxf(di * (acc0.x + acc1.x) + b.x, 0.0f);
    r.y = fmaxf(di * (acc0.y + acc1.y) + b.y, 0.0f);
    r.z = fmaxf(di * (acc0.z + acc1.z) + b.z, 0.0f);
    r.w = fmaxf(di * (acc0.w + acc1.w) + b.w, 0.0f);
    reinterpret_cast<float4*>(g_h)[node * 32 + lane] = r;
}

__global__ void __launch_bounds__(256) k_agg2(const float* __restrict__ b2,
                                              float* __restrict__ out) {
    __shared__ Edge tile[8][32];
    int wid  = threadIdx.x >> 5;
    int lane = threadIdx.x & 31;
    int node = blockIdx.x * 8 + wid;
    if (node >= NN) return;

    const float2* hw2 = reinterpret_cast<const float2*>(g_hw);
    float di = g_dinv[node];
    float2 self = hw2[node * 32 + lane];
    float2 acc0 = make_float2(di * self.x, di * self.y);
    float2 acc1 = make_float2(0.f, 0.f);

    int beg = g_rowptr[node], end = g_rowptr[node + 1];
    for (int t = beg; t < end; t += 32) {
        int n = min(32, end - t);
        Edge e;
        if (t + lane < end) {
            e = g_csr[t + lane];
            e.c *= g_dinv[e.s];
        }
        __syncwarp();
        if (t + lane < end) tile[wid][lane] = e;
        __syncwarp();
        if (n == 32) {
            for (int j = 0; j < 32; j += 4) {
                Edge e0 = tile[wid][j + 0];
                Edge e1 = tile[wid][j + 1];
                Edge e2 = tile[wid][j + 2];
                Edge e3 = tile[wid][j + 3];
                float2 v0 = hw2[e0.s * 32 + lane];
                float2 v1 = hw2[e1.s * 32 + lane];
                float2 v2 = hw2[e2.s * 32 + lane];
                float2 v3 = hw2[e3.s * 32 + lane];
                acc0.x += e0.c * v0.x; acc0.y += e0.c * v0.y;
                acc1.x += e1.c * v1.x; acc1.y += e1.c * v1.y;
                acc0.x += e2.c * v2.x; acc0.y += e2.c * v2.y;
                acc1.x += e3.c * v3.x; acc1.y += e3.c * v3.y;
            }
        } else {
            for (int j = 0; j < n; j++) {
                Edge e0 = tile[wid][j];
                float2 v = hw2[e0.s * 32 + lane];
                acc0.x += e0.c * v.x; acc0.y += e0.c * v.y;
            }
        }
    }

    float2 b = reinterpret_cast<const float2*>(b2)[lane];
    float2 r;
    r.x = di * (acc0.x + acc1.x) + b.x;
    r.y = di * (acc0.y + acc1.y) + b.y;
    reinterpret_cast<float2*>(out)[node * 32 + lane] = r;
}

// ---------------------------------------------------------------------------
// launch: default = CSR chain; s1 = GEMM1; s2 = dinv (after count)
// ---------------------------------------------------------------------------
extern "C" void kernel_launch(void* const* d_in, const int* in_sizes, int n_in,
                              void* d_out, int out_size) {
    const float* x    = (const float*)d_in[0];
    const int*   ei32 = (const int*)d_in[1];
    const float* w    = (const float*)d_in[2];
    const float* W1   = (const float*)d_in[3];
    const float* b1   = (const float*)d_in[4];
    const float* W2   = (const float*)d_in[5];
    const float* b2   = (const float*)d_in[6];
    float* out = (float*)d_out;

    // created once on the (uncaptured) correctness call; reused under capture
    static cudaStream_t s1 = nullptr, s2 = nullptr;
    static cudaEvent_t evFork = nullptr, evG1 = nullptr, evCnt = nullptr, evDinv = nullptr;
    if (s1 == nullptr) {
        cudaStreamCreateWithFlags(&s1, cudaStreamNonBlocking);
        cudaStreamCreateWithFlags(&s2, cudaStreamNonBlocking);
        cudaEventCreateWithFlags(&evFork, cudaEventDisableTiming);
        cudaEventCreateWithFlags(&evG1,   cudaEventDisableTiming);
        cudaEventCreateWithFlags(&evCnt,  cudaEventDisableTiming);
        cudaEventCreateWithFlags(&evDinv, cudaEventDisableTiming);
    }

    const int T = 256;

    // fork GEMM1 (independent of graph pipeline)
    cudaEventRecord(evFork, 0);
    cudaStreamWaitEvent(s1, evFork, 0);
    {
        dim3 grid((NN + 63) / 64, C_HID / 64);
        k_gemm1<<<grid, 256, 0, s1>>>(x, W1);
    }
    cudaEventRecord(evG1, s1);

    // CSR build (default stream)
    k_zero_detect<<<(NN + T - 1) / T, T>>>(ei32);
    k_count<<<(NE + T - 1) / T, T>>>(ei32, w);
    cudaEventRecord(evCnt, 0);

    // dinv on side stream, overlapped with scan+fill
    cudaStreamWaitEvent(s2, evCnt, 0);
    k_dinv_ew<<<(NN + T - 1) / T, T, 0, s2>>>();
    cudaEventRecord(evDinv, s2);

    k_scan<<<1, 1024>>>();
    k_fill<<<(NE + T - 1) / T, T>>>(w);

    // join: agg1 needs csr + dinv + xw
    cudaStreamWaitEvent(0, evDinv, 0);
    cudaStreamWaitEvent(0, evG1, 0);

    k_agg1<<<(NN + 7) / 8, 256>>>(b1);
    {
        dim3 grid((NN + 63) / 64, C_OUT / 64);
        k_gemm2<<<grid, 256>>>(W2);
    }
    k_agg2<<<(NN + 7) / 8, 256>>>(b2, out);
}

// round 9
// speedup vs baseline: 1.0196x; 1.0196x over previous
#include <cuda_runtime.h>
#include <cuda_bf16.h>

constexpr int NN  = 10000;
constexpr int NE  = 640000;
constexpr int C_IN  = 128;
constexpr int C_HID = 128;
constexpr int C_OUT = 64;

struct __align__(8) Edge { int s; float c; };

// Scratch (device globals — no allocation allowed)
__device__ __align__(256) float g_deg [NN];
__device__ __align__(256) float g_dinv[NN];
__device__ __align__(256) int   g_count[NN];
__device__ __align__(256) int   g_rowptr[NN + 1];
__device__ __align__(256) int   g_sd  [NE];       // packed (s | d<<16)
__device__ __align__(256) int   g_rank[NE];
__device__ __align__(256) Edge  g_csr [NE];
__device__ __align__(256) float g_xw  [NN * C_HID];  // x @ W1 (unscaled)
__device__ __align__(256) float g_h   [NN * C_HID];  // relu(layer1 out)
__device__ __align__(256) float g_hw  [NN * C_OUT];  // h @ W2 (unscaled)

// edge_index dtype: 0 -> int64 (odd 32-bit words all zero), 1 -> int32.
__device__ int g_odd_nonzero;

__device__ __forceinline__ int load_idx(const int* __restrict__ ei32, long pos) {
    return (g_odd_nonzero == 0) ? ei32[2 * pos] : ei32[pos];
}

// ---------------------------------------------------------------------------
// zero counters/degree + detect dtype
// ---------------------------------------------------------------------------
__global__ void k_zero_detect(const int* __restrict__ ei32) {
    int i = blockIdx.x * blockDim.x + threadIdx.x;
    if (i < NN) { g_count[i] = 0; g_deg[i] = 1.0f; }  // 1.0 = self-loop weight
    if (i < 2048) {
        if (ei32[2 * i + 1] != 0) atomicOr(&g_odd_nonzero, 1);
    }
}

// ---------------------------------------------------------------------------
// count + rank + pack (1 atomic per edge) — lean, on critical path
// ---------------------------------------------------------------------------
__global__ void k_count(const int* __restrict__ ei32) {
    int e = blockIdx.x * blockDim.x + threadIdx.x;
    if (e < NE) {
        int s = load_idx(ei32, e);
        int d = load_idx(ei32, (long)NE + e);
        s = min(max(s, 0), NN - 1);
        d = min(max(d, 0), NN - 1);
        g_sd[e] = s | (d << 16);
        g_rank[e] = atomicAdd(&g_count[d], 1);
    }
}

// weighted degree (returnless atomics -> REDG) — side stream, off critical path
__global__ void k_deg(const int* __restrict__ ei32,
                      const float* __restrict__ w) {
    int e = blockIdx.x * blockDim.x + threadIdx.x;
    if (e < NE) {
        int d = load_idx(ei32, (long)NE + e);
        d = min(max(d, 0), NN - 1);
        atomicAdd(&g_deg[d], w[e]);
    }
}

__global__ void k_dinv_ew() {
    int i = blockIdx.x * blockDim.x + threadIdx.x;
    if (i < NN) g_dinv[i] = rsqrtf(g_deg[i]);
}

// warp-shuffle exclusive scan of g_count -> g_rowptr (1024 thr, 2 barriers)
__global__ void k_scan() {
    constexpr int T = 1024, ITEMS = 10;   // 1024*10 >= 10000
    __shared__ int wsum[32];
    int t = threadIdx.x;
    int lane = t & 31;
    int wid  = t >> 5;

    int base = t * ITEMS;
    int local[ITEMS];
    int sum = 0;
#pragma unroll
    for (int i = 0; i < ITEMS; i++) {
        int idx = base + i;
        int v = (idx < NN) ? g_count[idx] : 0;
        local[i] = sum;
        sum += v;
    }
    int tsum = sum;

    int incl = tsum;
#pragma unroll
    for (int off = 1; off < 32; off <<= 1) {
        int v = __shfl_up_sync(0xFFFFFFFF, incl, off);
        if (lane >= off) incl += v;
    }
    if (lane == 31) wsum[wid] = incl;
    __syncthreads();
    if (wid == 0) {
        int s = wsum[lane];
#pragma unroll
        for (int off = 1; off < 32; off <<= 1) {
            int u = __shfl_up_sync(0xFFFFFFFF, s, off);
            if (lane >= off) s += u;
        }
        wsum[lane] = s;   // inclusive over warps
    }
    __syncthreads();

    int warpBase = (wid > 0) ? wsum[wid - 1] : 0;
    int texcl = warpBase + incl - tsum;
#pragma unroll
    for (int i = 0; i < ITEMS; i++) {
        int idx = base + i;
        if (idx < NN) g_rowptr[idx] = texcl + local[i];
    }
    if (t == T - 1) g_rowptr[NN] = wsum[31];
}

// fill CSR (no atomics)
__global__ void k_fill(const float* __restrict__ w) {
    int e = blockIdx.x * blockDim.x + threadIdx.x;
    if (e < NE) {
        int sd = g_sd[e];
        int s = sd & 0xFFFF;
        int d = sd >> 16;
        int pos = g_rowptr[d] + g_rank[e];
        Edge ed; ed.s = s; ed.c = w[e];
        g_csr[pos] = ed;
    }
}

// ---------------------------------------------------------------------------
// fp32 tiled GEMM (pure):  C = A @ B
// ---------------------------------------------------------------------------
__device__ __forceinline__ void gemm_body(const float* __restrict__ A,
                                          const float* __restrict__ B,
                                          float* __restrict__ C,
                                          int M, int N, int K) {
    constexpr int BM = 64, BN = 64, BK = 16;
    __shared__ float As[BK][BM];
    __shared__ float Bs[BK][BN];

    int rowBase = blockIdx.x * BM;
    int colBase = blockIdx.y * BN;
    int tx = threadIdx.x % 16;
    int ty = threadIdx.x / 16;

    float acc[4][4];
#pragma unroll
    for (int m = 0; m < 4; m++)
#pragma unroll
        for (int n = 0; n < 4; n++) acc[m][n] = 0.0f;

    for (int k0 = 0; k0 < K; k0 += BK) {
        for (int i = threadIdx.x; i < BM * BK; i += 256) {
            int r = i / BK, c = i % BK;
            int gr = rowBase + r;
            As[c][r] = (gr < M) ? A[(long)gr * K + k0 + c] : 0.0f;
        }
        for (int i = threadIdx.x; i < BK * BN; i += 256) {
            int r = i / BN, c = i % BN;
            Bs[r][c] = B[(long)(k0 + r) * N + colBase + c];
        }
        __syncthreads();

#pragma unroll
        for (int k = 0; k < BK; k++) {
            float a[4], b[4];
#pragma unroll
            for (int m = 0; m < 4; m++) a[m] = As[k][ty * 4 + m];
#pragma unroll
            for (int n = 0; n < 4; n++) b[n] = Bs[k][tx * 4 + n];
#pragma unroll
            for (int m = 0; m < 4; m++)
#pragma unroll
                for (int n = 0; n < 4; n++) acc[m][n] += a[m] * b[n];
        }
        __syncthreads();
    }

#pragma unroll
    for (int m = 0; m < 4; m++) {
        int gr = rowBase + ty * 4 + m;
        if (gr < M) {
#pragma unroll
            for (int n = 0; n < 4; n++)
                C[(long)gr * N + colBase + tx * 4 + n] = acc[m][n];
        }
    }
}

__global__ void k_gemm1(const float* __restrict__ x,
                        const float* __restrict__ W1) {
    gemm_body(x, W1, g_xw, NN, C_HID, C_IN);
}
__global__ void k_gemm2(const float* __restrict__ W2) {
    gemm_body(g_h, W2, g_hw, NN, C_OUT, C_HID);
}

// ---------------------------------------------------------------------------
// warp-per-node gather-aggregate; dinv applied at staging + epilogue
//   out[d,:] = relu( dinv[d]*( dinv[d]*xw[d,:] + sum_e (w_e*dinv[s])*xw[s,:] ) + b )
// ---------------------------------------------------------------------------
__global__ void __launch_bounds__(256) k_agg1(const float* __restrict__ b1) {
    __shared__ Edge tile[8][32];
    int wid  = threadIdx.x >> 5;
    int lane = threadIdx.x & 31;
    int node = blockIdx.x * 8 + wid;
    if (node >= NN) return;

    const float4* xw4 = reinterpret_cast<const float4*>(g_xw);
    float di = g_dinv[node];
    float4 self = xw4[node * 32 + lane];
    float4 acc0 = make_float4(di * self.x, di * self.y, di * self.z, di * self.w);
    float4 acc1 = make_float4(0.f, 0.f, 0.f, 0.f);

    int beg = g_rowptr[node], end = g_rowptr[node + 1];
    for (int t = beg; t < end; t += 32) {
        int n = min(32, end - t);
        Edge e;
        if (t + lane < end) {
            e = g_csr[t + lane];
            e.c *= g_dinv[e.s];
        }
        __syncwarp();
        if (t + lane < end) tile[wid][lane] = e;
        __syncwarp();
        if (n == 32) {
            for (int j = 0; j < 32; j += 4) {
                Edge e0 = tile[wid][j + 0];
                Edge e1 = tile[wid][j + 1];
                Edge e2 = tile[wid][j + 2];
                Edge e3 = tile[wid][j + 3];
                float4 v0 = xw4[e0.s * 32 + lane];
                float4 v1 = xw4[e1.s * 32 + lane];
                float4 v2 = xw4[e2.s * 32 + lane];
                float4 v3 = xw4[e3.s * 32 + lane];
                acc0.x += e0.c * v0.x; acc0.y += e0.c * v0.y;
                acc0.z += e0.c * v0.z; acc0.w += e0.c * v0.w;
                acc1.x += e1.c * v1.x; acc1.y += e1.c * v1.y;
                acc1.z += e1.c * v1.z; acc1.w += e1.c * v1.w;
                acc0.x += e2.c * v2.x; acc0.y += e2.c * v2.y;
                acc0.z += e2.c * v2.z; acc0.w += e2.c * v2.w;
                acc1.x += e3.c * v3.x; acc1.y += e3.c * v3.y;
                acc1.z += e3.c * v3.z; acc1.w += e3.c * v3.w;
            }
        } else {
            for (int j = 0; j < n; j++) {
                Edge e0 = tile[wid][j];
                float4 v = xw4[e0.s * 32 + lane];
                acc0.x += e0.c * v.x; acc0.y += e0.c * v.y;
                acc0.z += e0.c * v.z; acc0.w += e0.c * v.w;
            }
        }
    }

    float4 b = reinterpret_cast<const float4*>(b1)[lane];
    float4 r;
    r.x = fmaxf(di * (acc0.x + acc1.x) + b.x, 0.0f);
    r.y = fmaxf(di * (acc0.y + acc1.y) + b.y, 0.0f);
    r.z = fmaxf(di * (acc0.z + acc1.z) + b.z, 0.0f);
    r.w = fmaxf(di * (acc0.w + acc1.w) + b.w, 0.0f);
    reinterpret_cast<float4*>(g_h)[node * 32 + lane] = r;
}

__global__ void __launch_bounds__(256) k_agg2(const float* __restrict__ b2,
                                              float* __restrict__ out) {
    __shared__ Edge tile[8][32];
    int wid  = threadIdx.x >> 5;
    int lane = threadIdx.x & 31;
    int node = blockIdx.x * 8 + wid;
    if (node >= NN) return;

    const float2* hw2 = reinterpret_cast<const float2*>(g_hw);
    float di = g_dinv[node];
    float2 self = hw2[node * 32 + lane];
    float2 acc0 = make_float2(di * self.x, di * self.y);
    float2 acc1 = make_float2(0.f, 0.f);

    int beg = g_rowptr[node], end = g_rowptr[node + 1];
    for (int t = beg; t < end; t += 32) {
        int n = min(32, end - t);
        Edge e;
        if (t + lane < end) {
            e = g_csr[t + lane];
            e.c *= g_dinv[e.s];
        }
        __syncwarp();
        if (t + lane < end) tile[wid][lane] = e;
        __syncwarp();
        if (n == 32) {
            for (int j = 0; j < 32; j += 4) {
                Edge e0 = tile[wid][j + 0];
                Edge e1 = tile[wid][j + 1];
                Edge e2 = tile[wid][j + 2];
                Edge e3 = tile[wid][j + 3];
                float2 v0 = hw2[e0.s * 32 + lane];
                float2 v1 = hw2[e1.s * 32 + lane];
                float2 v2 = hw2[e2.s * 32 + lane];
                float2 v3 = hw2[e3.s * 32 + lane];
                acc0.x += e0.c * v0.x; acc0.y += e0.c * v0.y;
                acc1.x += e1.c * v1.x; acc1.y += e1.c * v1.y;
                acc0.x += e2.c * v2.x; acc0.y += e2.c * v2.y;
                acc1.x += e3.c * v3.x; acc1.y += e3.c * v3.y;
            }
        } else {
            for (int j = 0; j < n; j++) {
                Edge e0 = tile[wid][j];
                float2 v = hw2[e0.s * 32 + lane];
                acc0.x += e0.c * v.x; acc0.y += e0.c * v.y;
            }
        }
    }

    float2 b = reinterpret_cast<const float2*>(b2)[lane];
    float2 r;
    r.x = di * (acc0.x + acc1.x) + b.x;
    r.y = di * (acc0.y + acc1.y) + b.y;
    reinterpret_cast<float2*>(out)[node * 32 + lane] = r;
}

// ---------------------------------------------------------------------------
// launch: default = CSR chain; s1 = GEMM1; s2 = deg+dinv
// ---------------------------------------------------------------------------
extern "C" void kernel_launch(void* const* d_in, const int* in_sizes, int n_in,
                              void* d_out, int out_size) {
    const float* x    = (const float*)d_in[0];
    const int*   ei32 = (const int*)d_in[1];
    const float* w    = (const float*)d_in[2];
    const float* W1   = (const float*)d_in[3];
    const float* b1   = (const float*)d_in[4];
    const float* W2   = (const float*)d_in[5];
    const float* b2   = (const float*)d_in[6];
    float* out = (float*)d_out;

    // created once on the (uncaptured) correctness call; reused under capture
    static cudaStream_t s1 = nullptr, s2 = nullptr;
    static cudaEvent_t evFork = nullptr, evG1 = nullptr, evZero = nullptr, evDinv = nullptr;
    if (s1 == nullptr) {
        cudaStreamCreateWithFlags(&s1, cudaStreamNonBlocking);
        cudaStreamCreateWithFlags(&s2, cudaStreamNonBlocking);
        cudaEventCreateWithFlags(&evFork, cudaEventDisableTiming);
        cudaEventCreateWithFlags(&evG1,   cudaEventDisableTiming);
        cudaEventCreateWithFlags(&evZero, cudaEventDisableTiming);
        cudaEventCreateWithFlags(&evDinv, cudaEventDisableTiming);
    }

    const int T = 256;

    // fork GEMM1 (independent of graph pipeline)
    cudaEventRecord(evFork, 0);
    cudaStreamWaitEvent(s1, evFork, 0);
    {
        dim3 grid((NN + 63) / 64, C_HID / 64);
        k_gemm1<<<grid, 256, 0, s1>>>(x, W1);
    }
    cudaEventRecord(evG1, s1);

    // CSR build (default stream)
    k_zero_detect<<<(NN + T - 1) / T, T>>>(ei32);
    cudaEventRecord(evZero, 0);

    // weighted degree + dinv on side stream, overlapped with count/scan/fill
    cudaStreamWaitEvent(s2, evZero, 0);
    k_deg<<<(NE + T - 1) / T, T, 0, s2>>>(ei32, w);
    k_dinv_ew<<<(NN + T - 1) / T, T, 0, s2>>>();
    cudaEventRecord(evDinv, s2);

    k_count<<<(NE + T - 1) / T, T>>>(ei32);
    k_scan<<<1, 1024>>>();
    k_fill<<<(NE + T - 1) / T, T>>>(w);

    // join: agg1 needs csr + dinv + xw
    cudaStreamWaitEvent(0, evDinv, 0);
    cudaStreamWaitEvent(0, evG1, 0);

    k_agg1<<<(NN + 7) / 8, 256>>>(b1);
    {
        dim3 grid((NN + 63) / 64, C_OUT / 64);
        k_gemm2<<<grid, 256>>>(W2);
    }
    k_agg2<<<(NN + 7) / 8, 256>>>(b2, out);
}

// round 10
// speedup vs baseline: 1.0595x; 1.0391x over previous
#include <cuda_runtime.h>
#include <cuda_fp16.h>

constexpr int NN  = 10000;
constexpr int NE  = 640000;
constexpr int C_IN  = 128;
constexpr int C_HID = 128;
constexpr int C_OUT = 64;

struct __align__(8) Edge { int s; float c; };

// Scratch (device globals — no allocation allowed)
__device__ __align__(256) float  g_deg [NN];
__device__ __align__(256) float  g_dinv[NN];
__device__ __align__(256) int    g_count[NN];
__device__ __align__(256) int    g_rowptr[NN + 1];
__device__ __align__(256) int    g_sd  [NE];       // packed (s | d<<16)
__device__ __align__(256) int    g_rank[NE];
__device__ __align__(256) Edge   g_csr [NE];
__device__ __align__(256) __half g_xwh [NN * C_HID];  // fp16(x @ W1)
__device__ __align__(256) float  g_h   [NN * C_HID];  // relu(layer1 out), fp32
__device__ __align__(256) __half g_hwh [NN * C_OUT];  // fp16(h @ W2)

// edge_index dtype: 0 -> int64 (odd 32-bit words all zero), 1 -> int32.
__device__ int g_odd_nonzero;

__device__ __forceinline__ int load_idx(const int* __restrict__ ei32, long pos) {
    return (g_odd_nonzero == 0) ? ei32[2 * pos] : ei32[pos];
}

// ---------------------------------------------------------------------------
// zero counters/degree + detect dtype
// ---------------------------------------------------------------------------
__global__ void k_zero_detect(const int* __restrict__ ei32) {
    int i = blockIdx.x * blockDim.x + threadIdx.x;
    if (i < NN) { g_count[i] = 0; g_deg[i] = 1.0f; }  // 1.0 = self-loop weight
    if (i < 2048) {
        if (ei32[2 * i + 1] != 0) atomicOr(&g_odd_nonzero, 1);
    }
}

// ---------------------------------------------------------------------------
// count + rank + pack + weighted degree (REDG)
// ---------------------------------------------------------------------------
__global__ void k_count(const int* __restrict__ ei32,
                        const float* __restrict__ w) {
    int e = blockIdx.x * blockDim.x + threadIdx.x;
    if (e < NE) {
        int s = load_idx(ei32, e);
        int d = load_idx(ei32, (long)NE + e);
        s = min(max(s, 0), NN - 1);
        d = min(max(d, 0), NN - 1);
        g_sd[e] = s | (d << 16);
        g_rank[e] = atomicAdd(&g_count[d], 1);
        atomicAdd(&g_deg[d], w[e]);   // no return -> REDG
    }
}

// warp-shuffle exclusive scan of g_count -> g_rowptr; also computes dinv
__global__ void k_scan() {
    constexpr int T = 1024, ITEMS = 10;   // 1024*10 >= 10000
    __shared__ int wsum[32];
    int t = threadIdx.x;
    int lane = t & 31;
    int wid  = t >> 5;

    int base = t * ITEMS;
    int local[ITEMS];
    int sum = 0;
#pragma unroll
    for (int i = 0; i < ITEMS; i++) {
        int idx = base + i;
        int v = (idx < NN) ? g_count[idx] : 0;
        local[i] = sum;
        sum += v;
    }
    int tsum = sum;

    int incl = tsum;
#pragma unroll
    for (int off = 1; off < 32; off <<= 1) {
        int v = __shfl_up_sync(0xFFFFFFFF, incl, off);
        if (lane >= off) incl += v;
    }
    if (lane == 31) wsum[wid] = incl;
    __syncthreads();
    if (wid == 0) {
        int s = wsum[lane];
#pragma unroll
        for (int off = 1; off < 32; off <<= 1) {
            int u = __shfl_up_sync(0xFFFFFFFF, s, off);
            if (lane >= off) s += u;
        }
        wsum[lane] = s;
    }
    __syncthreads();

    int warpBase = (wid > 0) ? wsum[wid - 1] : 0;
    int texcl = warpBase + incl - tsum;
#pragma unroll
    for (int i = 0; i < ITEMS; i++) {
        int idx = base + i;
        if (idx < NN) {
            g_rowptr[idx] = texcl + local[i];
            g_dinv[idx]   = rsqrtf(g_deg[idx]);   // deg final after k_count
        }
    }
    if (t == T - 1) g_rowptr[NN] = wsum[31];
}

// fill CSR (no atomics)
__global__ void k_fill(const float* __restrict__ w) {
    int e = blockIdx.x * blockDim.x + threadIdx.x;
    if (e < NE) {
        int sd = g_sd[e];
        int s = sd & 0xFFFF;
        int d = sd >> 16;
        int pos = g_rowptr[d] + g_rank[e];
        Edge ed; ed.s = s; ed.c = w[e];
        g_csr[pos] = ed;
    }
}

// ---------------------------------------------------------------------------
// fp32 tiled GEMM, fp16 output:  C = half(A @ B)
// ---------------------------------------------------------------------------
__device__ __forceinline__ void gemm_body_h(const float* __restrict__ A,
                                            const float* __restrict__ B,
                                            __half* __restrict__ C,
                                            int M, int N, int K) {
    constexpr int BM = 64, BN = 64, BK = 16;
    __shared__ float As[BK][BM];
    __shared__ float Bs[BK][BN];

    int rowBase = blockIdx.x * BM;
    int colBase = blockIdx.y * BN;
    int tx = threadIdx.x % 16;
    int ty = threadIdx.x / 16;

    float acc[4][4];
#pragma unroll
    for (int m = 0; m < 4; m++)
#pragma unroll
        for (int n = 0; n < 4; n++) acc[m][n] = 0.0f;

    for (int k0 = 0; k0 < K; k0 += BK) {
        for (int i = threadIdx.x; i < BM * BK; i += 256) {
            int r = i / BK, c = i % BK;
            int gr = rowBase + r;
            As[c][r] = (gr < M) ? A[(long)gr * K + k0 + c] : 0.0f;
        }
        for (int i = threadIdx.x; i < BK * BN; i += 256) {
            int r = i / BN, c = i % BN;
            Bs[r][c] = B[(long)(k0 + r) * N + colBase + c];
        }
        __syncthreads();

#pragma unroll
        for (int k = 0; k < BK; k++) {
            float a[4], b[4];
#pragma unroll
            for (int m = 0; m < 4; m++) a[m] = As[k][ty * 4 + m];
#pragma unroll
            for (int n = 0; n < 4; n++) b[n] = Bs[k][tx * 4 + n];
#pragma unroll
            for (int m = 0; m < 4; m++)
#pragma unroll
                for (int n = 0; n < 4; n++) acc[m][n] += a[m] * b[n];
        }
        __syncthreads();
    }

#pragma unroll
    for (int m = 0; m < 4; m++) {
        int gr = rowBase + ty * 4 + m;
        if (gr < M) {
            __half2 p0 = __floats2half2_rn(acc[m][0], acc[m][1]);
            __half2 p1 = __floats2half2_rn(acc[m][2], acc[m][3]);
            uint2 packed = make_uint2(*reinterpret_cast<unsigned*>(&p0),
                                      *reinterpret_cast<unsigned*>(&p1));
            *reinterpret_cast<uint2*>(C + (long)gr * N + colBase + tx * 4) = packed;
        }
    }
}

__global__ void k_gemm1(const float* __restrict__ x,
                        const float* __restrict__ W1) {
    gemm_body_h(x, W1, g_xwh, NN, C_HID, C_IN);
}
__global__ void k_gemm2(const float* __restrict__ W2) {
    gemm_body_h(g_h, W2, g_hwh, NN, C_OUT, C_HID);
}

// ---------------------------------------------------------------------------
// warp-per-node gather-aggregate over fp16 tables, fp32 accumulate
//   out[d,:] = relu( dinv[d]*( dinv[d]*xw[d,:] + sum_e (w_e*dinv[s])*xw[s,:] ) + b )
// ---------------------------------------------------------------------------
__device__ __forceinline__ float2 h2f(unsigned u) {
    __half2 h = *reinterpret_cast<__half2*>(&u);
    return __half22float2(h);
}

__global__ void __launch_bounds__(256) k_agg1(const float* __restrict__ b1) {
    __shared__ Edge tile[8][32];
    int wid  = threadIdx.x >> 5;
    int lane = threadIdx.x & 31;
    int node = blockIdx.x * 8 + wid;
    if (node >= NN) return;

    const uint2* xw = reinterpret_cast<const uint2*>(g_xwh);  // 4 half per uint2, 32/row
    float di = g_dinv[node];
    uint2 sr = xw[node * 32 + lane];
    float2 s0 = h2f(sr.x), s1 = h2f(sr.y);
    float4 acc0 = make_float4(di * s0.x, di * s0.y, di * s1.x, di * s1.y);
    float4 acc1 = make_float4(0.f, 0.f, 0.f, 0.f);

    int beg = g_rowptr[node], end = g_rowptr[node + 1];
    for (int t = beg; t < end; t += 32) {
        int n = min(32, end - t);
        Edge e;
        if (t + lane < end) {
            e = g_csr[t + lane];
            e.c *= g_dinv[e.s];
        }
        __syncwarp();
        if (t + lane < end) tile[wid][lane] = e;
        __syncwarp();
        if (n == 32) {
            for (int j = 0; j < 32; j += 4) {
                Edge e0 = tile[wid][j + 0];
                Edge e1 = tile[wid][j + 1];
                Edge e2 = tile[wid][j + 2];
                Edge e3 = tile[wid][j + 3];
                uint2 r0 = xw[e0.s * 32 + lane];
                uint2 r1 = xw[e1.s * 32 + lane];
                uint2 r2 = xw[e2.s * 32 + lane];
                uint2 r3 = xw[e3.s * 32 + lane];
                float2 a0 = h2f(r0.x), a1 = h2f(r0.y);
                acc0.x += e0.c * a0.x; acc0.y += e0.c * a0.y;
                acc0.z += e0.c * a1.x; acc0.w += e0.c * a1.y;
                float2 c0 = h2f(r1.x), c1 = h2f(r1.y);
                acc1.x += e1.c * c0.x; acc1.y += e1.c * c0.y;
                acc1.z += e1.c * c1.x; acc1.w += e1.c * c1.y;
                float2 d0 = h2f(r2.x), d1 = h2f(r2.y);
                acc0.x += e2.c * d0.x; acc0.y += e2.c * d0.y;
                acc0.z += e2.c * d1.x; acc0.w += e2.c * d1.y;
                float2 f0 = h2f(r3.x), f1 = h2f(r3.y);
                acc1.x += e3.c * f0.x; acc1.y += e3.c * f0.y;
                acc1.z += e3.c * f1.x; acc1.w += e3.c * f1.y;
            }
        } else {
            for (int j = 0; j < n; j++) {
                Edge e0 = tile[wid][j];
                uint2 r = xw[e0.s * 32 + lane];
                float2 a0 = h2f(r.x), a1 = h2f(r.y);
                acc0.x += e0.c * a0.x; acc0.y += e0.c * a0.y;
                acc0.z += e0.c * a1.x; acc0.w += e0.c * a1.y;
            }
        }
    }

    float4 b = reinterpret_cast<const float4*>(b1)[lane];
    float4 r;
    r.x = fmaxf(di * (acc0.x + acc1.x) + b.x, 0.0f);
    r.y = fmaxf(di * (acc0.y + acc1.y) + b.y, 0.0f);
    r.z = fmaxf(di * (acc0.z + acc1.z) + b.z, 0.0f);
    r.w = fmaxf(di * (acc0.w + acc1.w) + b.w, 0.0f);
    reinterpret_cast<float4*>(g_h)[node * 32 + lane] = r;
}

__global__ void __launch_bounds__(256) k_agg2(const float* __restrict__ b2,
                                              float* __restrict__ out) {
    __shared__ Edge tile[8][32];
    int wid  = threadIdx.x >> 5;
    int lane = threadIdx.x & 31;
    int node = blockIdx.x * 8 + wid;
    if (node >= NN) return;

    const unsigned* hw = reinterpret_cast<const unsigned*>(g_hwh);  // 2 half per u32, 32/row
    float di = g_dinv[node];
    float2 s = h2f(hw[node * 32 + lane]);
    float2 acc0 = make_float2(di * s.x, di * s.y);
    float2 acc1 = make_float2(0.f, 0.f);

    int beg = g_rowptr[node], end = g_rowptr[node + 1];
    for (int t = beg; t < end; t += 32) {
        int n = min(32, end - t);
        Edge e;
        if (t + lane < end) {
            e = g_csr[t + lane];
            e.c *= g_dinv[e.s];
        }
        __syncwarp();
        if (t + lane < end) tile[wid][lane] = e;
        __syncwarp();
        if (n == 32) {
            for (int j = 0; j < 32; j += 4) {
                Edge e0 = tile[wid][j + 0];
                Edge e1 = tile[wid][j + 1];
                Edge e2 = tile[wid][j + 2];
                Edge e3 = tile[wid][j + 3];
                float2 v0 = h2f(hw[e0.s * 32 + lane]);
                float2 v1 = h2f(hw[e1.s * 32 + lane]);
                float2 v2 = h2f(hw[e2.s * 32 + lane]);
                float2 v3 = h2f(hw[e3.s * 32 + lane]);
                acc0.x += e0.c * v0.x; acc0.y += e0.c * v0.y;
                acc1.x += e1.c * v1.x; acc1.y += e1.c * v1.y;
                acc0.x += e2.c * v2.x; acc0.y += e2.c * v2.y;
                acc1.x += e3.c * v3.x; acc1.y += e3.c * v3.y;
            }
        } else {
            for (int j = 0; j < n; j++) {
                Edge e0 = tile[wid][j];
                float2 v = h2f(hw[e0.s * 32 + lane]);
                acc0.x += e0.c * v.x; acc0.y += e0.c * v.y;
            }
        }
    }

    float2 b = reinterpret_cast<const float2*>(b2)[lane];
    float2 r;
    r.x = di * (acc0.x + acc1.x) + b.x;
    r.y = di * (acc0.y + acc1.y) + b.y;
    reinterpret_cast<float2*>(out)[node * 32 + lane] = r;
}

// ---------------------------------------------------------------------------
// launch: default = CSR chain; s1 = GEMM1. agg1 is the 6th issued kernel
// (visible to ncu's -s 5 -c 1 capture).
// ---------------------------------------------------------------------------
extern "C" void kernel_launch(void* const* d_in, const int* in_sizes, int n_in,
                              void* d_out, int out_size) {
    const float* x    = (const float*)d_in[0];
    const int*   ei32 = (const int*)d_in[1];
    const float* w    = (const float*)d_in[2];
    const float* W1   = (const float*)d_in[3];
    const float* b1   = (const float*)d_in[4];
    const float* W2   = (const float*)d_in[5];
    const float* b2   = (const float*)d_in[6];
    float* out = (float*)d_out;

    static cudaStream_t s1 = nullptr;
    static cudaEvent_t evFork = nullptr, evG1 = nullptr;
    if (s1 == nullptr) {
        cudaStreamCreateWithFlags(&s1, cudaStreamNonBlocking);
        cudaEventCreateWithFlags(&evFork, cudaEventDisableTiming);
        cudaEventCreateWithFlags(&evG1,   cudaEventDisableTiming);
    }

    const int T = 256;

    // (1) fork GEMM1 (independent of graph pipeline)
    cudaEventRecord(evFork, 0);
    cudaStreamWaitEvent(s1, evFork, 0);
    {
        dim3 grid((NN + 63) / 64, C_HID / 64);
        k_gemm1<<<grid, 256, 0, s1>>>(x, W1);
    }
    cudaEventRecord(evG1, s1);

    // (2..5) CSR build on default stream
    k_zero_detect<<<(NN + T - 1) / T, T>>>(ei32);
    k_count<<<(NE + T - 1) / T, T>>>(ei32, w);
    k_scan<<<1, 1024>>>();
    k_fill<<<(NE + T - 1) / T, T>>>(w);

    // join: agg1 needs csr + dinv + xwh
    cudaStreamWaitEvent(0, evG1, 0);

    // (6) agg1, (7) gemm2, (8) agg2
    k_agg1<<<(NN + 7) / 8, 256>>>(b1);
    {
        dim3 grid((NN + 63) / 64, C_OUT / 64);
        k_gemm2<<<grid, 256>>>(W2);
    }
    k_agg2<<<(NN + 7) / 8, 256>>>(b2, out);
}